// round 2
// baseline (speedup 1.0000x reference)
#include <cuda_runtime.h>

#define CI 64
#define DI 128
#define SS 16
#define RR 4
#define KK 4
#define HH 48
#define WW 48
#define LL 2304
#define TT 4
#define NCH 16
#define LCH 144

// ---------------- scratch (static device globals; no allocations) ----------------
__device__ float g_prev[CI*LL];
__device__ float g_cur [CI*LL];
__device__ float g_kl  [CI*LL];
__device__ float g_xln [TT*CI*LL];
__device__ float g_bias[TT*CI*LL];
__device__ float g_xz  [TT*2*DI*LL];
__device__ float g_xc  [TT*DI*LL];
__device__ float g_xcT [TT*DI*LL];
__device__ float g_dt  [TT*KK*DI*LL];
__device__ float g_Bt  [TT*KK*LL*SS];
__device__ float g_Ct  [TT*KK*LL*SS];
__device__ float g_y   [TT*KK*DI*LL];
__device__ float g_A   [2*KK*DI*SS];
__device__ float g_sumDs[2*DI];

// ---------------- helpers ----------------
__device__ __forceinline__ float red64_sum(float* sh, float v){
    int t = threadIdx.x;
    sh[t] = v; __syncthreads();
    #pragma unroll
    for (int o = 32; o > 0; o >>= 1){ if (t < o) sh[t] += sh[t+o]; __syncthreads(); }
    float r = sh[0]; __syncthreads(); return r;
}
__device__ __forceinline__ float red64_max(float* sh, float v){
    int t = threadIdx.x;
    sh[t] = v; __syncthreads();
    #pragma unroll
    for (int o = 32; o > 0; o >>= 1){ if (t < o) sh[t] = fmaxf(sh[t], sh[t+o]); __syncthreads(); }
    float r = sh[0]; __syncthreads(); return r;
}

// ---------------- precompute A = -exp(A_logs), sumDs ----------------
__global__ void k_precompute(const float* __restrict__ A_logs, const float* __restrict__ Ds){
    int i = blockIdx.x*blockDim.x + threadIdx.x;
    if (i < 2*KK*DI*SS) g_A[i] = -__expf(A_logs[i]);
    if (i < 2*DI){
        int m = i/DI, d = i%DI;
        float s = 0.f;
        #pragma unroll
        for (int k = 0; k < KK; k++) s += Ds[(m*KK+k)*DI + d];
        g_sumDs[i] = s;
    }
}

// ---------------- init: prev=LN(dz), cur=prev*exp(sigma), xln[t]=LN(img[t]) ----------------
__global__ void k_init(const float* __restrict__ dz, const float* __restrict__ sigma,
                       const float* __restrict__ img,
                       const float* __restrict__ niw, const float* __restrict__ nib,
                       const float* __restrict__ ndw, const float* __restrict__ ndb){
    __shared__ float sh[64];
    int l = blockIdx.x, c = threadIdx.x;
    float v   = dz[c*LL + l];
    float mu  = red64_sum(sh, v) * (1.f/CI);
    float d0  = v - mu;
    float var = red64_sum(sh, d0*d0) * (1.f/CI);
    float pv  = d0 * rsqrtf(var + 1e-6f) * ndw[c] + ndb[c];
    g_prev[c*LL + l] = pv;
    g_cur [c*LL + l] = pv * __expf(sigma[c*LL + l]);
    for (int t = 0; t < TT; t++){
        float x   = img[(t*CI + c)*LL + l];
        float mu2 = red64_sum(sh, x) * (1.f/CI);
        float dd  = x - mu2;
        float vv  = red64_sum(sh, dd*dd) * (1.f/CI);
        g_xln[(t*CI + c)*LL + l] = dd * rsqrtf(vv + 1e-6f) * niw[c] + nib[c];
    }
}

// ---------------- KL(cur, prev) per pixel over C ----------------
__global__ void k_kl(){
    __shared__ float sh[64];
    int l = blockIdx.x, c = threadIdx.x;
    float p = g_prev[c*LL + l], q = g_cur[c*LL + l];
    float mp = red64_max(sh, p);
    float sp = red64_sum(sh, __expf(p - mp));
    float lsep = mp + __logf(sp);
    float mq = red64_max(sh, q);
    float sq = red64_sum(sh, __expf(q - mq));
    float lseq = mq + __logf(sq);
    float lp = p - lsep, lq = q - lseq;
    g_kl[c*LL + l] = __expf(lp) * (lp - lq);
}

// ---------------- in-projection GEMM: xz[256,L] = W[256,64]@x[64,L]+b ----------------
// grid(18 ltiles of 128, 8 dtiles of 32, nb), block 128 = 32 lq x 4 dq, each thread 8d x 4l
__global__ void k_inproj(const float* __restrict__ in_w, const float* __restrict__ in_b,
                         int m, int srcsel){
    __shared__ float sx[64*128];
    __shared__ float swT[64*33];
    const int lt = blockIdx.x, dtile = blockIdx.y, b = blockIdx.z, tid = threadIdx.x;
    const float* src = (srcsel ? g_xln : g_kl) + b*CI*LL + lt*128;
    for (int j = tid; j < 64*128; j += 128){
        int c = j >> 7;               // l = tid (step 128)
        sx[j] = src[c*LL + tid];
    }
    for (int j = tid; j < 32*64; j += 128){
        int dp = j >> 6, c = j & 63;  // coalesced W read, padded transpose store
        swT[c*33 + dp] = __ldg(&in_w[(m*256 + dtile*32 + dp)*64 + c]);
    }
    __syncthreads();
    int lq = tid & 31, dq = tid >> 5;
    float acc[8][4];
    #pragma unroll
    for (int i = 0; i < 8; i++){
        float bb = __ldg(&in_b[m*256 + dtile*32 + dq*8 + i]);
        #pragma unroll
        for (int j = 0; j < 4; j++) acc[i][j] = bb;
    }
    #pragma unroll 4
    for (int c = 0; c < 64; c++){
        float4 xv = *(const float4*)&sx[c*128 + lq*4];
        float xa[4] = {xv.x, xv.y, xv.z, xv.w};
        float wv[8];
        #pragma unroll
        for (int i = 0; i < 8; i++) wv[i] = swT[c*33 + dq*8 + i];
        #pragma unroll
        for (int i = 0; i < 8; i++)
            #pragma unroll
            for (int j = 0; j < 4; j++) acc[i][j] += wv[i]*xa[j];
    }
    #pragma unroll
    for (int i = 0; i < 8; i++){
        int d = dtile*32 + dq*8 + i;
        float* o = g_xz + (b*2*DI + d)*LL + lt*128 + lq*4;
        *(float4*)o = make_float4(acc[i][0], acc[i][1], acc[i][2], acc[i][3]);
    }
}

// ---------------- depthwise 3x3 conv + bias + silu; emit row-major and transposed ----------------
__global__ void k_conv(const float* __restrict__ cw, const float* __restrict__ cb, int m){
    __shared__ float sc[48*49];
    int d = blockIdx.x, b = blockIdx.y, tid = threadIdx.x;
    const float* in = g_xz + (b*2*DI + d)*LL;
    float w9[9];
    #pragma unroll
    for (int j = 0; j < 9; j++) w9[j] = __ldg(&cw[(m*DI + d)*9 + j]);
    float bias = __ldg(&cb[m*DI + d]);
    for (int i = tid; i < LL; i += 256){
        int h = i/48, w = i%48;
        float acc = 0.f;
        #pragma unroll
        for (int ky = 0; ky < 3; ky++){
            int hy = h + ky - 1;
            if (hy < 0 || hy >= 48) continue;
            #pragma unroll
            for (int kx = 0; kx < 3; kx++){
                int wx = w + kx - 1;
                if (wx < 0 || wx >= 48) continue;
                acc += w9[ky*3+kx] * in[hy*48 + wx];
            }
        }
        acc += bias;
        acc = acc / (1.f + __expf(-acc));   // silu
        sc[h*49 + w] = acc;
    }
    __syncthreads();
    float* oc = g_xc  + (b*DI + d)*LL;
    float* ot = g_xcT + (b*DI + d)*LL;
    for (int i = tid; i < LL; i += 256){
        int h = i/48, w = i%48;
        oc[i] = sc[h*49 + w];
        ot[i] = sc[w*49 + h];
    }
}

// ---------------- x-projection + dt(softplus) + B/C transpose; grid(48,K,nb), block 192 ----------------
__global__ void k_xproj(const float* __restrict__ xpw, const float* __restrict__ dtw,
                        const float* __restrict__ dtb, int m){
    __shared__ float s1[DI*48];     // xs tile, later reused for xdbl[36][48]
    __shared__ float s2[36*DI];     // xp_w[k]
    int lt = blockIdx.x, k = blockIdx.y, b = blockIdx.z, tid = threadIdx.x;
    bool fwd = (k < 2);
    const float* src = ((k & 1) ? g_xcT : g_xc) + b*DI*LL;
    for (int j = tid; j < DI*48; j += 192){
        int d = j/48, ls = j%48;
        int gl = fwd ? (lt*48 + ls) : (LL-1 - (lt*48 + ls));
        s1[j] = src[d*LL + gl];
    }
    const float* wk = xpw + (m*KK + k)*36*DI;
    for (int j = tid; j < 36*DI; j += 192) s2[j] = __ldg(&wk[j]);
    __syncthreads();
    int ls = tid % 48, rg = tid / 48;      // rg in 0..3, r = rg*9+i
    float acc[9];
    #pragma unroll
    for (int i = 0; i < 9; i++) acc[i] = 0.f;
    for (int c = 0; c < DI; c++){
        float xv = s1[c*48 + ls];
        #pragma unroll
        for (int i = 0; i < 9; i++) acc[i] += s2[(rg*9 + i)*DI + c] * xv;
    }
    __syncthreads();
    #pragma unroll
    for (int i = 0; i < 9; i++) s1[(rg*9 + i)*48 + ls] = acc[i];
    __syncthreads();
    // dt = softplus(dt_w @ xdbl[0:4] + dt_b)
    const float* dwk = dtw + (m*KK + k)*DI*RR;
    const float* dbk = dtb + (m*KK + k)*DI;
    float* dto = g_dt + ((size_t)(b*KK + k)*DI)*LL + lt*48;
    #pragma unroll 4
    for (int i = 0; i < 32; i++){
        int d = rg + 4*i;
        float v = __ldg(&dbk[d]);
        #pragma unroll
        for (int r = 0; r < 4; r++) v += __ldg(&dwk[d*4 + r]) * s1[r*48 + ls];
        v = fmaxf(v, 0.f) + log1pf(__expf(-fabsf(v)));   // stable softplus
        dto[d*LL + ls] = v;
    }
    // B, C transposed to [l][s]
    float* bt = g_Bt + ((size_t)(b*KK + k)*LL + lt*48)*SS;
    float* ct = g_Ct + ((size_t)(b*KK + k)*LL + lt*48)*SS;
    for (int j = tid; j < 48*SS; j += 192){
        int lls = j/SS, s = j%SS;
        bt[lls*SS + s] = s1[(4 + s)*48 + lls];
        ct[lls*SS + s] = s1[(20 + s)*48 + lls];
    }
}

// ---------------- chunked scan + y = sum_s h*C (one kernel); grid(128,K,nb), block 256 = 16s x 16chunks ----------------
__global__ void k_scan(int m){
    __shared__ float sdt [LL];
    __shared__ float sdtx[LL];
    __shared__ float pA[256], pH[256], hI[256];
    int d = blockIdx.x, k = blockIdx.y, b = blockIdx.z, tid = threadIdx.x;
    int s = tid & 15, c = tid >> 4;
    const float* dtrow = g_dt + ((size_t)(b*KK + k)*DI + d)*LL;
    const float* xrow  = ((k & 1) ? g_xcT : g_xc) + (b*DI + d)*LL;
    bool fwd = (k < 2);
    for (int i = tid; i < LL; i += 256){
        float dv = dtrow[i];
        float xv = fwd ? xrow[i] : xrow[LL-1-i];
        sdt[i]  = dv;
        sdtx[i] = dv * xv;
    }
    __syncthreads();
    float Av = __ldg(&g_A[((m*KK + k)*DI + d)*SS + s]);
    const float* bt = g_Bt + ((size_t)(b*KK + k)*LL)*SS;
    const float* ct = g_Ct + ((size_t)(b*KK + k)*LL)*SS;
    // pass 1: chunk-local (aProd, hEnd)
    float ap = 1.f, h = 0.f;
    int l0 = c*LCH;
    #pragma unroll 4
    for (int i = 0; i < LCH; i++){
        int l = l0 + i;
        float da = __expf(Av * sdt[l]);
        ap *= da;
        h = da*h + sdtx[l] * __ldg(&bt[l*SS + s]);
    }
    pA[tid] = ap; pH[tid] = h;
    __syncthreads();
    // pass 2: serial scan over 16 chunk summaries (one thread per s)
    if (tid < 16){
        float hh = 0.f;
        #pragma unroll
        for (int cc = 0; cc < NCH; cc++){
            hI[cc*16 + tid] = hh;
            hh = pA[cc*16 + tid]*hh + pH[cc*16 + tid];
        }
    }
    __syncthreads();
    // pass 3: recompute with true h_init, reduce over s, write y (flip applied for k>=2)
    h = hI[tid];
    float* yrow = g_y + ((size_t)(b*KK + k)*DI + d)*LL;
    #pragma unroll 2
    for (int i = 0; i < LCH; i++){
        int l = l0 + i;
        float da = __expf(Av * sdt[l]);
        h = da*h + sdtx[l] * __ldg(&bt[l*SS + s]);
        float v = h * __ldg(&ct[l*SS + s]);
        v += __shfl_xor_sync(0xffffffffu, v, 1);
        v += __shfl_xor_sync(0xffffffffu, v, 2);
        v += __shfl_xor_sync(0xffffffffu, v, 4);
        v += __shfl_xor_sync(0xffffffffu, v, 8);
        if (s == 0){
            int ol = fwd ? l : (LL-1-l);
            yrow[ol] = v;
        }
    }
}

// ---------------- merge dirs + LN + silu(z) gate + out-proj + (recurrent update) ----------------
// grid(72, nb), block 256 = 32 lsub x 8 dg
__global__ void k_merge(const float* __restrict__ onw, const float* __restrict__ onb,
                        const float* __restrict__ ow,  const float* __restrict__ ob,
                        int m, int mode, int t, float* __restrict__ outp){
    __shared__ float syy[DI*32];
    __shared__ float red0[8*32], red1[8*32];
    int tid = threadIdx.x;
    int lsub = tid & 31, dg = tid >> 5;
    int b = blockIdx.y;
    int l = blockIdx.x*32 + lsub;
    int tl = (l % 48)*48 + l/48;
    float ps = 0.f, pq = 0.f;
    for (int i = 0; i < 16; i++){
        int d = dg*16 + i;
        const float* y0 = g_y + ((size_t)(b*KK + 0)*DI + d)*LL;
        const float* y1 = g_y + ((size_t)(b*KK + 1)*DI + d)*LL;
        const float* y2 = g_y + ((size_t)(b*KK + 2)*DI + d)*LL;
        const float* y3 = g_y + ((size_t)(b*KK + 3)*DI + d)*LL;
        float v = y0[l] + y2[l] + y1[tl] + y3[tl]
                + g_sumDs[m*DI + d] * g_xc[(b*DI + d)*LL + l];
        syy[d*32 + lsub] = v;
        ps += v; pq += v*v;
    }
    red0[dg*32 + lsub] = ps; red1[dg*32 + lsub] = pq;
    __syncthreads();
    if (dg == 0){
        float s0 = 0.f, s1 = 0.f;
        #pragma unroll
        for (int j = 0; j < 8; j++){ s0 += red0[j*32 + lsub]; s1 += red1[j*32 + lsub]; }
        float mu  = s0 * (1.f/DI);
        float var = s1 * (1.f/DI) - mu*mu;
        red0[lsub] = mu;
        red1[lsub] = rsqrtf(var + 1e-6f);
    }
    __syncthreads();
    float mu = red0[lsub], rs = red1[lsub];
    for (int i = 0; i < 16; i++){
        int d = dg*16 + i;
        float v  = syy[d*32 + lsub];
        float wn = (v - mu)*rs*__ldg(&onw[m*DI + d]) + __ldg(&onb[m*DI + d]);
        float z  = g_xz[(b*2*DI + DI + d)*LL + l];
        float sz = z / (1.f + __expf(-z));
        syy[d*32 + lsub] = wn * sz;
    }
    __syncthreads();
    int cg = dg;
    float acc[8];
    #pragma unroll
    for (int i = 0; i < 8; i++) acc[i] = __ldg(&ob[m*CI + cg*8 + i]);
    for (int d = 0; d < DI; d++){
        float v = syy[d*32 + lsub];
        #pragma unroll
        for (int i = 0; i < 8; i++) acc[i] += __ldg(&ow[(m*CI + cg*8 + i)*DI + d]) * v;
    }
    #pragma unroll
    for (int i = 0; i < 8; i++){
        int cc = cg*8 + i;
        if (mode == 1){
            g_bias[(b*CI + cc)*LL + l] = acc[i];
        } else {
            int idx = cc*LL + l;
            float co = g_cur[idx];
            g_prev[idx] = co;
            float nv = co * __expf(acc[i]) + g_bias[(t*CI + cc)*LL + l];
            g_cur[idx] = nv;
            if (outp) outp[idx] = nv;
        }
    }
}

// ---------------- launch ----------------
extern "C" void kernel_launch(void* const* d_in, const int* in_sizes, int n_in,
                              void* d_out, int out_size){
    const float* img    = (const float*)d_in[0];
    const float* dz     = (const float*)d_in[1];
    const float* sigma  = (const float*)d_in[2];
    const float* in_w   = (const float*)d_in[3];
    const float* in_b   = (const float*)d_in[4];
    const float* conv_w = (const float*)d_in[5];
    const float* conv_b = (const float*)d_in[6];
    const float* xp_w   = (const float*)d_in[7];
    const float* dt_w   = (const float*)d_in[8];
    const float* dt_b   = (const float*)d_in[9];
    const float* A_logs = (const float*)d_in[10];
    const float* Ds     = (const float*)d_in[11];
    const float* onw    = (const float*)d_in[12];
    const float* onb    = (const float*)d_in[13];
    const float* ow     = (const float*)d_in[14];
    const float* ob     = (const float*)d_in[15];
    const float* niw    = (const float*)d_in[16];
    const float* nib    = (const float*)d_in[17];
    const float* ndw    = (const float*)d_in[18];
    const float* ndb    = (const float*)d_in[19];
    float* outp = (float*)d_out;

    k_precompute<<<64, 256>>>(A_logs, Ds);
    k_init<<<LL, 64>>>(dz, sigma, img, niw, nib, ndw, ndb);

    // bias pipeline, all 4 frames batched (m = 1)
    k_inproj<<<dim3(18, 8, TT), 128>>>(in_w, in_b, 1, 1);
    k_conv  <<<dim3(DI, TT), 256>>>(conv_w, conv_b, 1);
    k_xproj <<<dim3(48, KK, TT), 192>>>(xp_w, dt_w, dt_b, 1);
    k_scan  <<<dim3(DI, KK, TT), 256>>>(1);
    k_merge <<<dim3(72, TT), 256>>>(onw, onb, ow, ob, 1, 1, 0, nullptr);

    // sequential recurrence (m = 0)
    for (int t = 0; t < TT; t++){
        k_kl    <<<LL, 64>>>();
        k_inproj<<<dim3(18, 8, 1), 128>>>(in_w, in_b, 0, 0);
        k_conv  <<<dim3(DI, 1), 256>>>(conv_w, conv_b, 0);
        k_xproj <<<dim3(48, KK, 1), 192>>>(xp_w, dt_w, dt_b, 0);
        k_scan  <<<dim3(DI, KK, 1), 256>>>(0);
        k_merge <<<dim3(72, 1), 256>>>(onw, onb, ow, ob, 0, 0, t,
                                       (t == TT-1) ? outp : nullptr);
    }
}